// round 9
// baseline (speedup 1.0000x reference)
#include <cuda_runtime.h>
#include <math.h>

#define NROWS 32
#define NCOLS 512
#define NTILES 16                 // 512 / 32
#define NJOBS  136                // NTILES*(NTILES+1)/2
#define BLOCKS_X 34               // NJOBS / 4 warps per block
#define TOTAL_BLOCKS (BLOCKS_X * NROWS)   // 1088
#define TSTW 256                  // tau / w merged table size, domain [0,1]
#define TSG 1024                  // g table size
#define G_MIN (-24.0f)
#define G_RANGE 64.0f             // g domain [-24, 40]
#define NB_TAU 8
#define NB_G 8
#define NB_W 6
#define W_FLOOR 0.001f

// ---------------- device scratch (no allocations allowed) ----------------
__device__ float4 d_tab_tw[TSTW];              // (tau0, dtau, w0, dw)
__device__ float2 d_tab_g[TSG];                // (g0, dg)
__device__ float2 d_rs[NROWS * NCOLS];         // (r or NaN-if-masked, normalized s)
__device__ float  d_part_sum[TOTAL_BLOCKS];    // per-block partials (always written)
__device__ float  d_part_cnt[TOTAL_BLOCKS];    // counts exact in float (< 2^24)
__device__ int    d_done;                      // last-block-done counter (reset by last block)

// fast-math activations (table build only; rel_err budget ~1e-3, measured 2e-7)
__device__ __forceinline__ float fsp(float z) {
    return fmaxf(z, 0.0f) + __logf(1.0f + __expf(-fabsf(z)));
}
__device__ __forceinline__ float fsg(float z) {
    return __fdividef(1.0f, 1.0f + __expf(-z));
}

// ---------------- kernel A: lerp tables + row normalization (fused) ----------
// block 0: 1280 table entries; block 1: one warp per row, masked mean/var norm.
__global__ void __launch_bounds__(1024) setup_kernel(
    const float* __restrict__ pred, const float* __restrict__ tg,
    const float* __restrict__ th_tau, const float* __restrict__ th_g,
    const float* __restrict__ th_w)
{
    int tid = threadIdx.x;
    if (blockIdx.x == 0) {
        for (int e = tid; e < TSTW + TSG; e += 1024) {
            if (e < TSTW) {
                float ct[NB_TAU], cw[NB_W];
#pragma unroll
                for (int i = 0; i < NB_TAU; i++) ct[i] = fsp(th_tau[i]);
#pragma unroll
                for (int i = 0; i < NB_W; i++)   cw[i] = fsp(th_w[i]);
                float h = 1.0f / (float)(TSTW - 1);
                float x = (float)e * h;
                float t0 = 0.f, t1 = 0.f, w0 = 0.f, w1 = 0.f;
#pragma unroll
                for (int i = 0; i < NB_TAU; i++) {
                    float sl = 0.5f + 3.5f * (float)i / (float)(NB_TAU - 1);
                    float bi = -2.0f + 4.0f * (float)i / (float)(NB_TAU - 1);
                    t0 += ct[i] * fsp(fmaf(x,     sl, bi));
                    t1 += ct[i] * fsp(fmaf(x + h, sl, bi));
                }
#pragma unroll
                for (int i = 0; i < NB_W; i++) {
                    float sl = 0.5f + 3.5f * (float)i / (float)(NB_W - 1);
                    float bi = -2.0f + 4.0f * (float)i / (float)(NB_W - 1);
                    w0 += cw[i] * fsg(fmaf(x,     sl, bi));
                    w1 += cw[i] * fsg(fmaf(x + h, sl, bi));
                }
                d_tab_tw[e] = make_float4(t0, t1 - t0, w0, w1 - w0);
            } else {
                int i = e - TSTW;
                float cg[NB_G];
#pragma unroll
                for (int u = 0; u < NB_G; u++) cg[u] = fsp(th_g[u]);
                float h = G_RANGE / (float)(TSG - 1);
                float x = G_MIN + (float)i * h;
                float v0 = 0.f, v1 = 0.f;
#pragma unroll
                for (int u = 0; u < NB_G; u++) {
                    float sl = 0.5f + 3.5f * (float)u / (float)(NB_G - 1);
                    float bi = -2.0f + 4.0f * (float)u / (float)(NB_G - 1);
                    v0 += cg[u] * fsp(fmaf(x,     sl, bi));
                    v1 += cg[u] * fsp(fmaf(x + h, sl, bi));
                }
                d_tab_g[i] = make_float2(v0, v1 - v0);
            }
        }
    } else {
        // one warp per row: masked mean/var normalization, write d_rs
        int w = tid >> 5, lane = tid & 31;
        const float* p = pred + w * NCOLS;
        const float* t = tg   + w * NCOLS;
        float lp[16], lt[16]; bool lm[16];
        float sum = 0.0f, ssq = 0.0f, cnt = 0.0f;
#pragma unroll
        for (int u = 0; u < 16; u++) {
            float tv = t[lane + 32 * u];
            bool  m  = fabsf(tv + 1.0f) > 1.00001e-5f;   // ~jnp.isclose(t,-1) negated
            float pv = p[lane + 32 * u];
            lp[u] = pv; lt[u] = tv; lm[u] = m;
            sum += m ? pv : 0.0f;
            ssq += m ? pv * pv : 0.0f;
            cnt += m ? 1.0f : 0.0f;
        }
#pragma unroll
        for (int o = 16; o; o >>= 1) {
            sum += __shfl_xor_sync(0xffffffffu, sum, o);
            ssq += __shfl_xor_sync(0xffffffffu, ssq, o);
            cnt += __shfl_xor_sync(0xffffffffu, cnt, o);
        }
        float denom = fmaxf(cnt, 1.0f);
        float mean  = sum / denom;
        float var   = ssq / denom - mean * mean;
        float inv   = rsqrtf(var + 1e-6f);
        const float qnan = __int_as_float(0x7fffffff);
#pragma unroll
        for (int u = 0; u < 16; u++)
            d_rs[w * NCOLS + lane + 32 * u] =
                make_float2(lm[u] ? lt[u] : qnan, (lp[u] - mean) * inv);
    }
}

// ---------------- kernel B: tiled pair loop + final (fused) ------------------
__global__ void __launch_bounds__(128, 8) pair_kernel(float* __restrict__ out) {
    __shared__ float2 sh_g[TSG];       // 8 KB
    __shared__ float4 sh_tw[TSTW];     // 4 KB
    __shared__ float2 sh_rs[NCOLS];    // 4 KB
    __shared__ float  red_f[4];
    __shared__ float  red_c[4];
    __shared__ int    sh_last;
    __shared__ float  s_num[32];
    __shared__ float  s_val[32];

    int tid  = threadIdx.x;
    int b    = blockIdx.y;
    int lane = tid & 31, warp = tid >> 5;

    // ---- slim prologue: bulk float4 copy of tables + this row (16 KB) ----
    {
        const float4* sg = (const float4*)d_tab_g;           float4* dg = (float4*)sh_g;
        const float4* st = (const float4*)d_tab_tw;          float4* dt = (float4*)sh_tw;
        const float4* sr = (const float4*)(d_rs + b * NCOLS); float4* dr = (float4*)sh_rs;
#pragma unroll
        for (int u = 0; u < 4; u++) dg[tid + 128 * u] = sg[tid + 128 * u];   // 512
        dt[tid] = st[tid]; dt[tid + 128] = st[tid + 128];                     // 256
        dr[tid] = sr[tid]; dr[tid + 128] = sr[tid + 128];                     // 256
    }
    __syncthreads();

    // ---- one 32x32 tile job per warp ----
    // jobs enumerate 0 <= ti <= tj < 16; diagonal tiles keep ii < lane.
    // Pair loss is symmetric under (i,j) swap so orientation is irrelevant.
    int jb = blockIdx.x * 4 + warp;   // 0 .. 135
    int ti = 0, rem = jb;
    while (rem >= NTILES - ti) { rem -= NTILES - ti; ti++; }
    int tj  = ti + rem;
    int lim = (ti == tj) ? lane : 32;

    float2 pj = sh_rs[tj * 32 + lane];    // register-resident j side
    const int ibase = ti * 32;
    const float inv_hg = (float)(TSG - 1) / G_RANGE;
    const float c0     = -G_MIN * inv_hg;

    float acc = 0.0f, cntf = 0.0f;
#pragma unroll 8
    for (int ii = 0; ii < 32; ii++) {
        float2 pi = sh_rs[ibase + ii];    // uniform address -> broadcast LDS.64
        float dr = pi.x - pj.x;
        float ds = pi.y - pj.y;
        // branchless keep: false for ties and NaN (masked rows)
        float kf = (((dr > 0.0f) | (dr < 0.0f)) & (ii < lim)) ? 1.0f : 0.0f;
        float tds = (dr > 0.0f) ? ds : -ds;          // t * ds
        float adr = fabsf(dr);
        float pt = fminf(adr, 1.0f) * (float)(TSTW - 1);   // fminf(NaN,1)=1 -> safe idx
        int   it = min((int)pt, TSTW - 2);
        float ft = pt - (float)it;
        float4 etw = sh_tw[it];                      // one LDS.128: tau + w
        float tau = fmaf(ft, etw.y, etw.x);
        float w   = W_FLOOR + fmaf(ft, etw.w, etw.z);
        float m   = tau - tds;
        float pg  = fmaxf(fmaf(m, inv_hg, c0), 0.0f);
        int   ig  = min((int)pg, TSG - 2);
        float fg  = pg - (float)ig;                  // frac>1 at top = exact linear ext
        float2 eg = sh_g[ig];
        float g   = fmaf(fg, eg.y, eg.x);
        acc  = fmaf(kf, g * w, acc);
        cntf += kf;
    }

#pragma unroll
    for (int o = 16; o; o >>= 1) {
        acc  += __shfl_xor_sync(0xffffffffu, acc, o);
        cntf += __shfl_xor_sync(0xffffffffu, cntf, o);
    }
    if (lane == 0) { red_f[warp] = acc; red_c[warp] = cntf; }
    __syncthreads();
    if (tid == 0) {
        float bs = red_f[0] + red_f[1] + red_f[2] + red_f[3];
        float bc = red_c[0] + red_c[1] + red_c[2] + red_c[3];
        int slot = b * BLOCKS_X + blockIdx.x;
        d_part_sum[slot] = bs;
        d_part_cnt[slot] = bc;
        __threadfence();
        int old = atomicAdd(&d_done, 1);
        sh_last = (old == TOTAL_BLOCKS - 1) ? 1 : 0;
    }
    __syncthreads();

    // ---- last block performs the final reduction (1088 partials) ----
    if (sh_last) {
        __threadfence();   // acquire: partials of all other blocks now visible
        volatile float* vs = d_part_sum;
        volatile float* vc = d_part_cnt;
        int row = tid >> 2;            // 32 rows x 4 lanes
        int sub = tid & 3;
        int base = row * BLOCKS_X;
        float ps = 0.0f, pc = 0.0f;
#pragma unroll
        for (int k = sub; k < BLOCKS_X; k += 4) { ps += vs[base + k]; pc += vc[base + k]; }
#pragma unroll
        for (int o = 2; o; o >>= 1) {  // reduce within 4-lane groups
            ps += __shfl_xor_sync(0xffffffffu, ps, o);
            pc += __shfl_xor_sync(0xffffffffu, pc, o);
        }
        if (sub == 0) {
            float denom = fmaxf(pc, 1.0f);
            float rl    = ps / denom;
            float valid = (pc > 0.0f) ? 1.0f : 0.0f;
            s_num[row] = rl * valid;
            s_val[row] = valid;
        }
        __syncthreads();
        if (tid < 32) {
            float n = s_num[tid], v = s_val[tid];
#pragma unroll
            for (int o = 16; o; o >>= 1) {
                n += __shfl_xor_sync(0xffffffffu, n, o);
                v += __shfl_xor_sync(0xffffffffu, v, o);
            }
            if (tid == 0) {
                out[0] = n / fmaxf(v, 1.0f);
                d_done = 0;            // reset for next graph replay (deterministic)
            }
        }
    }
}

// ---------------- launch ----------------
extern "C" void kernel_launch(void* const* d_in, const int* in_sizes, int n_in,
                              void* d_out, int out_size) {
    const float* pred   = (const float*)d_in[0];
    const float* tg     = (const float*)d_in[1];
    const float* th_tau = (const float*)d_in[2];
    const float* th_g   = (const float*)d_in[3];
    const float* th_w   = (const float*)d_in[4];

    setup_kernel<<<2, 1024>>>(pred, tg, th_tau, th_g, th_w);
    dim3 grid(BLOCKS_X, NROWS);
    pair_kernel<<<grid, 128>>>((float*)d_out);
}